// round 3
// baseline (speedup 1.0000x reference)
#include <cuda_runtime.h>
#include <cuda_bf16.h>
#include <math.h>

// Problem constants
#define BATCH   64
#define SEQ     197
#define HIDDEN  768
#define HEADS   12
#define HDIM    64
#define KRANK   64
#define MROWS   (BATCH * SEQ)          // 12608

// ---------------------------------------------------------------------------
// Scratch (no allocations allowed): device globals
// ---------------------------------------------------------------------------
__device__ float g_Q  [MROWS * HIDDEN];
__device__ float g_K  [MROWS * HIDDEN];
__device__ float g_V  [MROWS * HIDDEN];
__device__ float g_CTX[MROWS * HIDDEN];
__device__ float g_PK [BATCH * KRANK * HIDDEN];
__device__ float g_PV [BATCH * KRANK * HIDDEN];

// ---------------------------------------------------------------------------
// SGEMM: C[M,N] = A[M,K] @ B[K,N] + bias[N]
// 128x128 block tile, BK=16, 256 threads, 8x8 per-thread micro-tile
// (split 4+4 halves for conflict-light float4 smem reads)
// ---------------------------------------------------------------------------
#define BM 128
#define BN 128
#define BK 16

__global__ __launch_bounds__(256) void sgemm_bias(
    const float* __restrict__ A, const float* __restrict__ B,
    const float* __restrict__ bias, float* __restrict__ C,
    int M, int N, int K)
{
    __shared__ float As[BK][BM];   // transposed: As[k][m]
    __shared__ float Bs[BK][BN];

    const int tid  = threadIdx.x;
    const int row0 = blockIdx.y * BM;
    const int col0 = blockIdx.x * BN;
    const int tx   = tid & 15;     // 0..15
    const int ty   = tid >> 4;     // 0..15

    // A-load mapping: 2 float4 per thread (rows ar, ar+64; 4 cols)
    const int ar = tid >> 2;           // 0..63
    const int ac = (tid & 3) * 4;      // 0,4,8,12
    // B-load mapping: 2 float4 per thread (rows br, br+8)
    const int br = tid >> 5;           // 0..7
    const int bc = (tid & 31) * 4;     // 0..124

    float4 aR0, aR1, bR0, bR1;

    const float4 f4z = make_float4(0.f, 0.f, 0.f, 0.f);

    // prologue load (k0 = 0)
    {
        int m0 = row0 + ar, m1 = row0 + ar + 64;
        aR0 = (m0 < M) ? *(const float4*)(A + (long)m0 * K + ac) : f4z;
        aR1 = (m1 < M) ? *(const float4*)(A + (long)m1 * K + ac) : f4z;
        bR0 = *(const float4*)(B + (long)br * N + col0 + bc);
        bR1 = *(const float4*)(B + (long)(br + 8) * N + col0 + bc);
    }

    float acc[8][8];
    #pragma unroll
    for (int i = 0; i < 8; ++i)
        #pragma unroll
        for (int j = 0; j < 8; ++j) acc[i][j] = 0.f;

    const int nk = K / BK;
    for (int t = 0; t < nk; ++t) {
        // commit staged regs to smem
        As[ac + 0][ar]      = aR0.x;
        As[ac + 1][ar]      = aR0.y;
        As[ac + 2][ar]      = aR0.z;
        As[ac + 3][ar]      = aR0.w;
        As[ac + 0][ar + 64] = aR1.x;
        As[ac + 1][ar + 64] = aR1.y;
        As[ac + 2][ar + 64] = aR1.z;
        As[ac + 3][ar + 64] = aR1.w;
        *(float4*)&Bs[br][bc]     = bR0;
        *(float4*)&Bs[br + 8][bc] = bR1;
        __syncthreads();

        // prefetch next tile while computing
        if (t + 1 < nk) {
            int k0 = (t + 1) * BK;
            int m0 = row0 + ar, m1 = row0 + ar + 64;
            aR0 = (m0 < M) ? *(const float4*)(A + (long)m0 * K + k0 + ac) : f4z;
            aR1 = (m1 < M) ? *(const float4*)(A + (long)m1 * K + k0 + ac) : f4z;
            bR0 = *(const float4*)(B + (long)(k0 + br) * N + col0 + bc);
            bR1 = *(const float4*)(B + (long)(k0 + br + 8) * N + col0 + bc);
        }

        #pragma unroll
        for (int k = 0; k < BK; ++k) {
            float4 av0 = *(const float4*)&As[k][ty * 4];
            float4 av1 = *(const float4*)&As[k][64 + ty * 4];
            float4 bv0 = *(const float4*)&Bs[k][tx * 4];
            float4 bv1 = *(const float4*)&Bs[k][64 + tx * 4];
            float a[8] = {av0.x, av0.y, av0.z, av0.w, av1.x, av1.y, av1.z, av1.w};
            float b[8] = {bv0.x, bv0.y, bv0.z, bv0.w, bv1.x, bv1.y, bv1.z, bv1.w};
            #pragma unroll
            for (int i = 0; i < 8; ++i)
                #pragma unroll
                for (int j = 0; j < 8; ++j)
                    acc[i][j] = fmaf(a[i], b[j], acc[i][j]);
        }
        __syncthreads();
    }

    // epilogue: add bias, store (m-guarded)
    #pragma unroll
    for (int ih = 0; ih < 2; ++ih) {
        #pragma unroll
        for (int i = 0; i < 4; ++i) {
            int m = row0 + ih * 64 + ty * 4 + i;
            if (m >= M) continue;
            #pragma unroll
            for (int jh = 0; jh < 2; ++jh) {
                int n = col0 + jh * 64 + tx * 4;
                float4 v;
                v.x = acc[ih * 4 + i][jh * 4 + 0] + bias[n + 0];
                v.y = acc[ih * 4 + i][jh * 4 + 1] + bias[n + 1];
                v.z = acc[ih * 4 + i][jh * 4 + 2] + bias[n + 2];
                v.w = acc[ih * 4 + i][jh * 4 + 3] + bias[n + 3];
                *(float4*)(C + (long)m * N + n) = v;
            }
        }
    }
}

// ---------------------------------------------------------------------------
// Low-rank sequence projection:
//   OUT[b, k, c] = sum_s E[s,k] * SRC[(b*SEQ+s)*HIDDEN + c]
// grid = (HIDDEN/64, BATCH); 256 threads; thread = (c = tid&63, kgroup = tid>>6)
// ---------------------------------------------------------------------------
__global__ __launch_bounds__(256) void proj_lowrank(
    const float* __restrict__ E,    // [SEQ, KRANK]
    const float* __restrict__ SRC,  // [B*SEQ, HIDDEN]
    float* __restrict__ OUT)        // [B, KRANK, HIDDEN]
{
    const int cc = blockIdx.x;   // column chunk of 64
    const int b  = blockIdx.y;

    __shared__ float Es[16][64];
    __shared__ float Ks[16][64];

    const int tid = threadIdx.x;
    const int c   = tid & 63;
    const int kg  = tid >> 6;    // 0..3 -> k rows kg*16 .. kg*16+15

    float acc[16];
    #pragma unroll
    for (int i = 0; i < 16; ++i) acc[i] = 0.f;

    for (int s0 = 0; s0 < SEQ; s0 += 16) {
        #pragma unroll
        for (int i = 0; i < 4; ++i) {
            int idx = tid + i * 256;
            int r = idx >> 6, cl = idx & 63;
            int s = s0 + r;
            float ev = 0.f, kv = 0.f;
            if (s < SEQ) {
                ev = E[s * KRANK + cl];
                kv = SRC[((long)b * SEQ + s) * HIDDEN + cc * 64 + cl];
            }
            Es[r][cl] = ev;
            Ks[r][cl] = kv;
        }
        __syncthreads();

        #pragma unroll
        for (int s = 0; s < 16; ++s) {
            float kv = Ks[s][c];
            float4 e0 = *(const float4*)&Es[s][kg * 16 + 0];
            float4 e1 = *(const float4*)&Es[s][kg * 16 + 4];
            float4 e2 = *(const float4*)&Es[s][kg * 16 + 8];
            float4 e3 = *(const float4*)&Es[s][kg * 16 + 12];
            acc[0]  = fmaf(e0.x, kv, acc[0]);
            acc[1]  = fmaf(e0.y, kv, acc[1]);
            acc[2]  = fmaf(e0.z, kv, acc[2]);
            acc[3]  = fmaf(e0.w, kv, acc[3]);
            acc[4]  = fmaf(e1.x, kv, acc[4]);
            acc[5]  = fmaf(e1.y, kv, acc[5]);
            acc[6]  = fmaf(e1.z, kv, acc[6]);
            acc[7]  = fmaf(e1.w, kv, acc[7]);
            acc[8]  = fmaf(e2.x, kv, acc[8]);
            acc[9]  = fmaf(e2.y, kv, acc[9]);
            acc[10] = fmaf(e2.z, kv, acc[10]);
            acc[11] = fmaf(e2.w, kv, acc[11]);
            acc[12] = fmaf(e3.x, kv, acc[12]);
            acc[13] = fmaf(e3.y, kv, acc[13]);
            acc[14] = fmaf(e3.z, kv, acc[14]);
            acc[15] = fmaf(e3.w, kv, acc[15]);
        }
        __syncthreads();
    }

    #pragma unroll
    for (int kk = 0; kk < 16; ++kk)
        OUT[((long)b * KRANK + kg * 16 + kk) * HIDDEN + cc * 64 + c] = acc[kk];
}

// ---------------------------------------------------------------------------
// Fused low-rank attention per (b,h):
//   scores[s,k] = scale * <Q[b,s,h,:], PK[b,k,h,:]>   (k-rank = 64)
//   probs = softmax_k(scores);  CTX[b,s,h,:] = probs @ PV[b,:,h,:]
// 128 threads = 4 warps; one warp per query row.
// ---------------------------------------------------------------------------
__global__ __launch_bounds__(128) void lowrank_attn(
    const float* __restrict__ Q,   // [B*SEQ, HIDDEN]
    const float* __restrict__ PK,  // [B, KRANK, HIDDEN]
    const float* __restrict__ PV,  // [B, KRANK, HIDDEN]
    float* __restrict__ CTX)       // [B*SEQ, HIDDEN]
{
    const int h = blockIdx.x;
    const int b = blockIdx.y;

    __shared__ float pk_s[64 * 65];   // [k][d] pad-65: lanes across k conflict-free
    __shared__ float pv_s[64 * 64];   // [k][d]: lanes across d conflict-free
    __shared__ float qs[4][64];
    __shared__ float ps[4][64];

    const int tid  = threadIdx.x;
    const int w    = tid >> 5;
    const int lane = tid & 31;

    const float* pkg = PK + ((long)b * KRANK) * HIDDEN + h * HDIM;
    const float* pvg = PV + ((long)b * KRANK) * HIDDEN + h * HDIM;
    for (int i = tid; i < 64 * 64; i += 128) {
        int k = i >> 6, d = i & 63;
        pk_s[k * 65 + d] = pkg[(long)k * HIDDEN + d];
        pv_s[k * 64 + d] = pvg[(long)k * HIDDEN + d];
    }
    __syncthreads();

    const float scale = 0.125f;   // 1/sqrt(64)

    for (int s = w; s < SEQ; s += 4) {
        const float* qg = Q + ((long)b * SEQ + s) * HIDDEN + h * HDIM;
        qs[w][lane]      = qg[lane];
        qs[w][lane + 32] = qg[lane + 32];
        __syncwarp();

        // scores for k = lane and k = lane+32
        float s0 = 0.f, s1 = 0.f;
        const float* p0 = &pk_s[lane * 65];
        const float* p1 = &pk_s[(lane + 32) * 65];
        #pragma unroll
        for (int d = 0; d < 64; ++d) {
            float qd = qs[w][d];
            s0 = fmaf(qd, p0[d], s0);
            s1 = fmaf(qd, p1[d], s1);
        }
        s0 *= scale; s1 *= scale;

        // softmax over 64 entries distributed 2-per-lane
        float mx = fmaxf(s0, s1);
        #pragma unroll
        for (int o = 16; o > 0; o >>= 1)
            mx = fmaxf(mx, __shfl_xor_sync(0xffffffffu, mx, o));
        float e0 = expf(s0 - mx);
        float e1 = expf(s1 - mx);
        float sm = e0 + e1;
        #pragma unroll
        for (int o = 16; o > 0; o >>= 1)
            sm += __shfl_xor_sync(0xffffffffu, sm, o);
        float inv = 1.f / sm;
        ps[w][lane]      = e0 * inv;
        ps[w][lane + 32] = e1 * inv;
        __syncwarp();

        // ctx for d = lane and d = lane+32
        float c0 = 0.f, c1 = 0.f;
        #pragma unroll
        for (int k = 0; k < 64; ++k) {
            float p = ps[w][k];
            c0 = fmaf(p, pv_s[k * 64 + lane],      c0);
            c1 = fmaf(p, pv_s[k * 64 + lane + 32], c1);
        }
        float* cg = CTX + ((long)b * SEQ + s) * HIDDEN + h * HDIM;
        cg[lane]      = c0;
        cg[lane + 32] = c1;
        __syncwarp();
    }
}

// ---------------------------------------------------------------------------
// Launch orchestration
// ---------------------------------------------------------------------------
extern "C" void kernel_launch(void* const* d_in, const int* in_sizes, int n_in,
                              void* d_out, int out_size)
{
    const float* hs = (const float*)d_in[0];
    const float* Wq = (const float*)d_in[1];
    const float* bq = (const float*)d_in[2];
    const float* Wk = (const float*)d_in[3];
    const float* bk = (const float*)d_in[4];
    const float* Wv = (const float*)d_in[5];
    const float* bv = (const float*)d_in[6];
    const float* Wo = (const float*)d_in[7];
    const float* bo = (const float*)d_in[8];
    const float* Ek = (const float*)d_in[9];
    const float* Ev = (const float*)d_in[10];
    float* out = (float*)d_out;

    float *pQ, *pK, *pV, *pCTX, *pPK, *pPV;
    cudaGetSymbolAddress((void**)&pQ,   g_Q);
    cudaGetSymbolAddress((void**)&pK,   g_K);
    cudaGetSymbolAddress((void**)&pV,   g_V);
    cudaGetSymbolAddress((void**)&pCTX, g_CTX);
    cudaGetSymbolAddress((void**)&pPK,  g_PK);
    cudaGetSymbolAddress((void**)&pPV,  g_PV);

    dim3 gemmGrid(HIDDEN / BN, (MROWS + BM - 1) / BM);   // (6, 99)
    dim3 gemmBlk(256);

    sgemm_bias<<<gemmGrid, gemmBlk>>>(hs, Wq, bq, pQ, MROWS, HIDDEN, HIDDEN);
    sgemm_bias<<<gemmGrid, gemmBlk>>>(hs, Wk, bk, pK, MROWS, HIDDEN, HIDDEN);
    sgemm_bias<<<gemmGrid, gemmBlk>>>(hs, Wv, bv, pV, MROWS, HIDDEN, HIDDEN);

    dim3 projGrid(HIDDEN / 64, BATCH);                   // (12, 64)
    proj_lowrank<<<projGrid, 256>>>(Ek, pK, pPK);
    proj_lowrank<<<projGrid, 256>>>(Ev, pV, pPV);

    dim3 attnGrid(HEADS, BATCH);                          // (12, 64)
    lowrank_attn<<<attnGrid, 128>>>(pQ, pPK, pPV, pCTX);

    sgemm_bias<<<gemmGrid, gemmBlk>>>(pCTX, Wo, bo, out, MROWS, HIDDEN, HIDDEN);
}

// round 7
// speedup vs baseline: 2.2382x; 2.2382x over previous
#include <cuda_runtime.h>
#include <cuda_bf16.h>
#include <cstdint>
#include <math.h>

// Problem constants
#define BATCH   64
#define SEQ     197
#define HIDDEN  768
#define HEADS   12
#define HDIM    64
#define KRANK   64
#define MROWS   (BATCH * SEQ)          // 12608
#define HH      (HIDDEN * HIDDEN)

// ---------------------------------------------------------------------------
// Scratch (no allocations allowed): device globals
// ---------------------------------------------------------------------------
__device__ float g_Q  [MROWS * HIDDEN];
__device__ float g_K  [MROWS * HIDDEN];
__device__ float g_V  [MROWS * HIDDEN];
__device__ float g_CTX[MROWS * HIDDEN];
__device__ float g_PK [BATCH * KRANK * HIDDEN];
__device__ float g_PV [BATCH * KRANK * HIDDEN];
__device__ float g_Ar [MROWS * HIDDEN];   // tf32-rounded activations
__device__ float g_Wt [4 * HH];           // transposed + tf32-rounded weights [n][k]

// ---------------------------------------------------------------------------
// Helpers
// ---------------------------------------------------------------------------
static __device__ __forceinline__ uint32_t smem_u32(const void* p) {
    uint32_t a;
    asm("{ .reg .u64 t; cvta.to.shared.u64 t, %1; cvt.u32.u64 %0, t; }"
        : "=r"(a) : "l"(p));
    return a;
}
static __device__ __forceinline__ void cpa16(uint32_t s, const void* g) {
    asm volatile("cp.async.cg.shared.global [%0], [%1], 16;" :: "r"(s), "l"(g));
}
static __device__ __forceinline__ float rna_tf32(float x) {
    uint32_t u;
    asm("cvt.rna.tf32.f32 %0, %1;" : "=r"(u) : "f"(x));
    return __uint_as_float(u);
}
static __device__ __forceinline__ void mma_tf32(
    float* c, const uint32_t* a, const uint32_t* b)
{
    asm volatile(
        "mma.sync.aligned.m16n8k8.row.col.f32.tf32.tf32.f32 "
        "{%0,%1,%2,%3}, {%4,%5,%6,%7}, {%8,%9}, {%0,%1,%2,%3};"
        : "+f"(c[0]), "+f"(c[1]), "+f"(c[2]), "+f"(c[3])
        : "r"(a[0]), "r"(a[1]), "r"(a[2]), "r"(a[3]), "r"(b[0]), "r"(b[1]));
}

// ---------------------------------------------------------------------------
// tf32 HMMA GEMM: C[M,768] = A[M,768] @ W + bias  (W given transposed [n][k])
// CTA tile 128x128, 8 warps (2x4, warp tile 64x32), K-chunk 32, 3-stage
// cp.async pipeline. A/W pre-rounded to tf32 (rna).
// Smem per stage: A 128x36 fp32 (pad) + B 128x36 fp32 = 36864 B; 3 stages.
// ---------------------------------------------------------------------------
#define LDP 36                     // padded row stride (floats)
#define STAGE_F (2 * 128 * LDP)    // floats per stage = 9216
#define GEMM_SMEM (3 * STAGE_F * 4)  // 110592 bytes

__global__ __launch_bounds__(256, 1) void gemm_tf32(
    const float* __restrict__ A, const float* __restrict__ Bt,
    const float* __restrict__ bias, float* __restrict__ C)
{
    extern __shared__ float sm[];
    const int tid  = threadIdx.x;
    const int wid  = tid >> 5;
    const int lane = tid & 31;
    const int gid  = lane >> 2;    // 0..7
    const int tg   = lane & 3;     // 0..3
    const int wm   = (wid >> 2) * 64;   // warp m offset in CTA tile
    const int wn   = (wid & 3) * 32;    // warp n offset
    const int row0 = blockIdx.y * 128;
    const int col0 = blockIdx.x * 128;

    // gmem load mapping: 4 iterations x 256 threads = 1024 16B copies per tile
    const int lrow = tid >> 3;     // 0..31 (+32*i)
    const int lseg = tid & 7;      // 0..7 -> floats seg*4..seg*4+3

    float acc[4][4][4];
    #pragma unroll
    for (int i = 0; i < 4; ++i)
        #pragma unroll
        for (int j = 0; j < 4; ++j)
            #pragma unroll
            for (int r = 0; r < 4; ++r) acc[i][j][r] = 0.f;

#define LOAD_STAGE(s, t) do {                                                  \
    const int _k0 = (t) * 32;                                                  \
    float* _dA = sm + (s) * STAGE_F;                                           \
    float* _dB = _dA + 128 * LDP;                                              \
    _Pragma("unroll")                                                          \
    for (int _i = 0; _i < 4; ++_i) {                                           \
        int _row = lrow + _i * 32;                                             \
        int _ar = row0 + _row; if (_ar > MROWS - 1) _ar = MROWS - 1;           \
        cpa16(smem_u32(_dA + _row * LDP + lseg * 4),                           \
              A + (long)_ar * HIDDEN + _k0 + lseg * 4);                        \
        cpa16(smem_u32(_dB + _row * LDP + lseg * 4),                           \
              Bt + (long)(col0 + _row) * HIDDEN + _k0 + lseg * 4);             \
    }                                                                          \
    asm volatile("cp.async.commit_group;" ::: "memory");                       \
} while (0)

    LOAD_STAGE(0, 0);
    LOAD_STAGE(1, 1);

    for (int t = 0; t < 24; ++t) {
        if (t + 2 < 24) {
            LOAD_STAGE((t + 2) % 3, t + 2);
            asm volatile("cp.async.wait_group 2;" ::: "memory");
        } else if (t == 22) {
            asm volatile("cp.async.wait_group 1;" ::: "memory");
        } else {
            asm volatile("cp.async.wait_group 0;" ::: "memory");
        }
        __syncthreads();

        const float* As = sm + (t % 3) * STAGE_F;
        const float* Bs = As + 128 * LDP;

        #pragma unroll
        for (int k8 = 0; k8 < 4; ++k8) {
            const int kb = k8 * 8;
            uint32_t a[4][4], b[4][2];
            #pragma unroll
            for (int mi = 0; mi < 4; ++mi) {
                const int r = wm + mi * 16 + gid;
                a[mi][0] = __float_as_uint(As[r       * LDP + kb + tg]);
                a[mi][1] = __float_as_uint(As[(r + 8) * LDP + kb + tg]);
                a[mi][2] = __float_as_uint(As[r       * LDP + kb + tg + 4]);
                a[mi][3] = __float_as_uint(As[(r + 8) * LDP + kb + tg + 4]);
            }
            #pragma unroll
            for (int nj = 0; nj < 4; ++nj) {
                const int n = wn + nj * 8 + gid;
                b[nj][0] = __float_as_uint(Bs[n * LDP + kb + tg]);
                b[nj][1] = __float_as_uint(Bs[n * LDP + kb + tg + 4]);
            }
            #pragma unroll
            for (int mi = 0; mi < 4; ++mi)
                #pragma unroll
                for (int nj = 0; nj < 4; ++nj)
                    mma_tf32(acc[mi][nj], a[mi], b[nj]);
        }
        __syncthreads();
    }

    // epilogue: direct stores + bias (float2 per fragment row)
    #pragma unroll
    for (int nj = 0; nj < 4; ++nj) {
        const int cb = col0 + wn + nj * 8 + tg * 2;
        const float bx = bias[cb];
        const float by = bias[cb + 1];
        #pragma unroll
        for (int mi = 0; mi < 4; ++mi) {
            const int r = row0 + wm + mi * 16 + gid;
            if (r < MROWS) {
                float2 v = make_float2(acc[mi][nj][0] + bx, acc[mi][nj][1] + by);
                *(float2*)(C + (long)r * HIDDEN + cb) = v;
            }
            if (r + 8 < MROWS) {
                float2 v = make_float2(acc[mi][nj][2] + bx, acc[mi][nj][3] + by);
                *(float2*)(C + (long)(r + 8) * HIDDEN + cb) = v;
            }
        }
    }
}

// ---------------------------------------------------------------------------
// Elementwise tf32 (rna) rounding, float4 vectorized
// ---------------------------------------------------------------------------
__global__ __launch_bounds__(256) void round_tf32(
    const float* __restrict__ X, float* __restrict__ Y, int n4)
{
    int i = blockIdx.x * 256 + threadIdx.x;
    if (i >= n4) return;
    float4 x = ((const float4*)X)[i];
    x.x = rna_tf32(x.x); x.y = rna_tf32(x.y);
    x.z = rna_tf32(x.z); x.w = rna_tf32(x.w);
    ((float4*)Y)[i] = x;
}

// ---------------------------------------------------------------------------
// Weight transpose + tf32 round: W[k][n] -> T[n][k]
// ---------------------------------------------------------------------------
__global__ __launch_bounds__(256) void wtrans_round(
    const float* __restrict__ W, float* __restrict__ T)
{
    __shared__ float t[32][33];
    const int bx = blockIdx.x * 32;   // n
    const int by = blockIdx.y * 32;   // k
    const int x = threadIdx.x & 31, y = threadIdx.x >> 5;   // 32 x 8
    #pragma unroll
    for (int i = 0; i < 32; i += 8)
        t[y + i][x] = W[(by + y + i) * HIDDEN + bx + x];
    __syncthreads();
    #pragma unroll
    for (int i = 0; i < 32; i += 8)
        T[(bx + y + i) * HIDDEN + by + x] = rna_tf32(t[x][y + i]);
}

// ---------------------------------------------------------------------------
// Low-rank sequence projection (fp32, from the passing R3 kernel)
// ---------------------------------------------------------------------------
__global__ __launch_bounds__(256) void proj_lowrank(
    const float* __restrict__ E, const float* __restrict__ SRC,
    float* __restrict__ OUT)
{
    const int cc = blockIdx.x;
    const int b  = blockIdx.y;

    __shared__ float Es[16][64];
    __shared__ float Ks[16][64];

    const int tid = threadIdx.x;
    const int c   = tid & 63;
    const int kg  = tid >> 6;

    float acc[16];
    #pragma unroll
    for (int i = 0; i < 16; ++i) acc[i] = 0.f;

    for (int s0 = 0; s0 < SEQ; s0 += 16) {
        #pragma unroll
        for (int i = 0; i < 4; ++i) {
            int idx = tid + i * 256;
            int r = idx >> 6, cl = idx & 63;
            int s = s0 + r;
            float ev = 0.f, kv = 0.f;
            if (s < SEQ) {
                ev = E[s * KRANK + cl];
                kv = SRC[((long)b * SEQ + s) * HIDDEN + cc * 64 + cl];
            }
            Es[r][cl] = ev;
            Ks[r][cl] = kv;
        }
        __syncthreads();

        #pragma unroll
        for (int s = 0; s < 16; ++s) {
            float kv = Ks[s][c];
            float4 e0 = *(const float4*)&Es[s][kg * 16 + 0];
            float4 e1 = *(const float4*)&Es[s][kg * 16 + 4];
            float4 e2 = *(const float4*)&Es[s][kg * 16 + 8];
            float4 e3 = *(const float4*)&Es[s][kg * 16 + 12];
            acc[0]  = fmaf(e0.x, kv, acc[0]);
            acc[1]  = fmaf(e0.y, kv, acc[1]);
            acc[2]  = fmaf(e0.z, kv, acc[2]);
            acc[3]  = fmaf(e0.w, kv, acc[3]);
            acc[4]  = fmaf(e1.x, kv, acc[4]);
            acc[5]  = fmaf(e1.y, kv, acc[5]);
            acc[6]  = fmaf(e1.z, kv, acc[6]);
            acc[7]  = fmaf(e1.w, kv, acc[7]);
            acc[8]  = fmaf(e2.x, kv, acc[8]);
            acc[9]  = fmaf(e2.y, kv, acc[9]);
            acc[10] = fmaf(e2.z, kv, acc[10]);
            acc[11] = fmaf(e2.w, kv, acc[11]);
            acc[12] = fmaf(e3.x, kv, acc[12]);
            acc[13] = fmaf(e3.y, kv, acc[13]);
            acc[14] = fmaf(e3.z, kv, acc[14]);
            acc[15] = fmaf(e3.w, kv, acc[15]);
        }
        __syncthreads();
    }

    #pragma unroll
    for (int kk = 0; kk < 16; ++kk)
        OUT[((long)b * KRANK + kg * 16 + kk) * HIDDEN + cc * 64 + c] = acc[kk];
}

// ---------------------------------------------------------------------------
// Fused low-rank attention per (b,h) (fp32, from the passing R3 kernel)
// ---------------------------------------------------------------------------
__global__ __launch_bounds__(128) void lowrank_attn(
    const float* __restrict__ Q, const float* __restrict__ PK,
    const float* __restrict__ PV, float* __restrict__ CTX)
{
    const int h = blockIdx.x;
    const int b = blockIdx.y;

    __shared__ float pk_s[64 * 65];
    __shared__ float pv_s[64 * 64];
    __shared__ float qs[4][64];
    __shared__ float ps[4][64];

    const int tid  = threadIdx.x;
    const int w    = tid >> 5;
    const int lane = tid & 31;

    const float* pkg = PK + ((long)b * KRANK) * HIDDEN + h * HDIM;
    const float* pvg = PV + ((long)b * KRANK) * HIDDEN + h * HDIM;
    for (int i = tid; i < 64 * 64; i += 128) {
        int k = i >> 6, d = i & 63;
        pk_s[k * 65 + d] = pkg[(long)k * HIDDEN + d];
        pv_s[k * 64 + d] = pvg[(long)k * HIDDEN + d];
    }
    __syncthreads();

    const float scale = 0.125f;

    for (int s = w; s < SEQ; s += 4) {
        const float* qg = Q + ((long)b * SEQ + s) * HIDDEN + h * HDIM;
        qs[w][lane]      = qg[lane];
        qs[w][lane + 32] = qg[lane + 32];
        __syncwarp();

        float s0 = 0.f, s1 = 0.f;
        const float* p0 = &pk_s[lane * 65];
        const float* p1 = &pk_s[(lane + 32) * 65];
        #pragma unroll
        for (int d = 0; d < 64; ++d) {
            float qd = qs[w][d];
            s0 = fmaf(qd, p0[d], s0);
            s1 = fmaf(qd, p1[d], s1);
        }
        s0 *= scale; s1 *= scale;

        float mx = fmaxf(s0, s1);
        #pragma unroll
        for (int o = 16; o > 0; o >>= 1)
            mx = fmaxf(mx, __shfl_xor_sync(0xffffffffu, mx, o));
        float e0 = expf(s0 - mx);
        float e1 = expf(s1 - mx);
        float sm = e0 + e1;
        #pragma unroll
        for (int o = 16; o > 0; o >>= 1)
            sm += __shfl_xor_sync(0xffffffffu, sm, o);
        float inv = 1.f / sm;
        ps[w][lane]      = e0 * inv;
        ps[w][lane + 32] = e1 * inv;
        __syncwarp();

        float c0 = 0.f, c1 = 0.f;
        #pragma unroll
        for (int k = 0; k < 64; ++k) {
            float p = ps[w][k];
            c0 = fmaf(p, pv_s[k * 64 + lane],      c0);
            c1 = fmaf(p, pv_s[k * 64 + lane + 32], c1);
        }
        float* cg = CTX + ((long)b * SEQ + s) * HIDDEN + h * HDIM;
        cg[lane]      = c0;
        cg[lane + 32] = c1;
        __syncwarp();
    }
}

// ---------------------------------------------------------------------------
// Launch orchestration
// ---------------------------------------------------------------------------
extern "C" void kernel_launch(void* const* d_in, const int* in_sizes, int n_in,
                              void* d_out, int out_size)
{
    const float* hs = (const float*)d_in[0];
    const float* Wq = (const float*)d_in[1];
    const float* bq = (const float*)d_in[2];
    const float* Wk = (const float*)d_in[3];
    const float* bk = (const float*)d_in[4];
    const float* Wv = (const float*)d_in[5];
    const float* bv = (const float*)d_in[6];
    const float* Wo = (const float*)d_in[7];
    const float* bo = (const float*)d_in[8];
    const float* Ek = (const float*)d_in[9];
    const float* Ev = (const float*)d_in[10];
    float* out = (float*)d_out;

    float *pQ, *pK, *pV, *pCTX, *pPK, *pPV, *pAr, *pWt;
    cudaGetSymbolAddress((void**)&pQ,   g_Q);
    cudaGetSymbolAddress((void**)&pK,   g_K);
    cudaGetSymbolAddress((void**)&pV,   g_V);
    cudaGetSymbolAddress((void**)&pCTX, g_CTX);
    cudaGetSymbolAddress((void**)&pPK,  g_PK);
    cudaGetSymbolAddress((void**)&pPV,  g_PV);
    cudaGetSymbolAddress((void**)&pAr,  g_Ar);
    cudaGetSymbolAddress((void**)&pWt,  g_Wt);

    cudaFuncSetAttribute(gemm_tf32, cudaFuncAttributeMaxDynamicSharedMemorySize,
                         GEMM_SMEM);

    const int n4 = MROWS * HIDDEN / 4;
    dim3 tgrid(HIDDEN / 32, HIDDEN / 32);             // (24,24)
    dim3 ggrid(HIDDEN / 128, (MROWS + 127) / 128);    // (6, 99)

    // prep: round activations, transpose+round weights
    round_tf32<<<(n4 + 255) / 256, 256>>>(hs, pAr, n4);
    wtrans_round<<<tgrid, 256>>>(Wq, pWt + 0 * HH);
    wtrans_round<<<tgrid, 256>>>(Wk, pWt + 1 * HH);
    wtrans_round<<<tgrid, 256>>>(Wv, pWt + 2 * HH);
    wtrans_round<<<tgrid, 256>>>(Wo, pWt + 3 * HH);

    // QKV projections on tensor cores (tf32 HMMA)
    gemm_tf32<<<ggrid, 256, GEMM_SMEM>>>(pAr, pWt + 0 * HH, bq, pQ);
    gemm_tf32<<<ggrid, 256, GEMM_SMEM>>>(pAr, pWt + 1 * HH, bk, pK);
    gemm_tf32<<<ggrid, 256, GEMM_SMEM>>>(pAr, pWt + 2 * HH, bv, pV);

    // low-rank projections + attention (fp32)
    dim3 projGrid(HIDDEN / 64, BATCH);
    proj_lowrank<<<projGrid, 256>>>(Ek, pK, pPK);
    proj_lowrank<<<projGrid, 256>>>(Ev, pV, pPV);

    dim3 attnGrid(HEADS, BATCH);
    lowrank_attn<<<attnGrid, 128>>>(pQ, pPK, pPV, pCTX);

    // output projection
    round_tf32<<<(n4 + 255) / 256, 256>>>(pCTX, pAr, n4);
    gemm_tf32<<<ggrid, 256, GEMM_SMEM>>>(pAr, pWt + 3 * HH, bo, out);
}

// round 8
// speedup vs baseline: 2.6470x; 1.1826x over previous
#include <cuda_runtime.h>
#include <cuda_bf16.h>
#include <cstdint>
#include <math.h>

// Problem constants
#define BATCH   64
#define SEQ     197
#define HIDDEN  768
#define HEADS   12
#define HDIM    64
#define KRANK   64
#define MROWS   (BATCH * SEQ)          // 12608
#define HH      (HIDDEN * HIDDEN)
#define KPAD    224                    // SEQ padded to 7*32

// ---------------------------------------------------------------------------
// Scratch (no allocations allowed): device globals
// ---------------------------------------------------------------------------
__device__ float g_Q  [MROWS * HIDDEN];
__device__ float g_K  [MROWS * HIDDEN];
__device__ float g_V  [MROWS * HIDDEN];
__device__ float g_CTX[MROWS * HIDDEN];
__device__ float g_PK [BATCH * KRANK * HIDDEN];
__device__ float g_PV [BATCH * KRANK * HIDDEN];
__device__ float g_Wt [4 * HH];            // transposed + tf32-rounded weights [n][k]
__device__ float g_Et [2 * KRANK * KPAD];  // E^T, tf32-rounded, zero-padded

// ---------------------------------------------------------------------------
// Helpers
// ---------------------------------------------------------------------------
static __device__ __forceinline__ uint32_t smem_u32(const void* p) {
    uint32_t a;
    asm("{ .reg .u64 t; cvta.to.shared.u64 t, %1; cvt.u32.u64 %0, t; }"
        : "=r"(a) : "l"(p));
    return a;
}
static __device__ __forceinline__ void cpa16(uint32_t s, const void* g) {
    asm volatile("cp.async.cg.shared.global [%0], [%1], 16;" :: "r"(s), "l"(g));
}
static __device__ __forceinline__ float rna_tf32(float x) {
    uint32_t u;
    asm("cvt.rna.tf32.f32 %0, %1;" : "=r"(u) : "f"(x));
    return __uint_as_float(u);
}
static __device__ __forceinline__ uint32_t rna_u(float x) {
    uint32_t u;
    asm("cvt.rna.tf32.f32 %0, %1;" : "=r"(u) : "f"(x));
    return u;
}
static __device__ __forceinline__ void mma_tf32(
    float* c, const uint32_t* a, const uint32_t* b)
{
    asm volatile(
        "mma.sync.aligned.m16n8k8.row.col.f32.tf32.tf32.f32 "
        "{%0,%1,%2,%3}, {%4,%5,%6,%7}, {%8,%9}, {%0,%1,%2,%3};"
        : "+f"(c[0]), "+f"(c[1]), "+f"(c[2]), "+f"(c[3])
        : "r"(a[0]), "r"(a[1]), "r"(a[2]), "r"(a[3]), "r"(b[0]), "r"(b[1]));
}

struct GSet { const float* Bt; const float* bias; float* C; };

// ---------------------------------------------------------------------------
// tf32 HMMA GEMM: C[M,768] = A[M,768] @ W + bias  (W transposed [n][k],
// pre-rounded; A raw fp32, rounded per-fragment in registers).
// CTA 128x128, 8 warps (2x4, warp tile 64x32), K-chunk 32, 3-stage cp.async,
// ONE __syncthreads per chunk, register double-buffered fragments.
// blockIdx.z selects among 3 (Bt, bias, C) sets sharing the same A.
// ---------------------------------------------------------------------------
#define LDP 36
#define STAGE_F (2 * 128 * LDP)          // 9216 floats
#define GEMM_SMEM (3 * STAGE_F * 4)      // 110592 bytes

__global__ __launch_bounds__(256, 1) void gemm_tf32(
    const float* __restrict__ A, GSet s0, GSet s1, GSet s2)
{
    extern __shared__ float sm[];
    const GSet g = (blockIdx.z == 0) ? s0 : (blockIdx.z == 1) ? s1 : s2;
    const float* __restrict__ Bt   = g.Bt;
    const float* __restrict__ bias = g.bias;
    float* __restrict__ C          = g.C;

    const int tid  = threadIdx.x;
    const int wid  = tid >> 5;
    const int lane = tid & 31;
    const int gid  = lane >> 2;
    const int tg   = lane & 3;
    const int wm   = (wid >> 2) * 64;
    const int wn   = (wid & 3) * 32;
    const int row0 = blockIdx.y * 128;
    const int col0 = blockIdx.x * 128;

    const int lrow = tid >> 3;
    const int lseg = tid & 7;

    float acc[4][4][4];
    #pragma unroll
    for (int i = 0; i < 4; ++i)
        #pragma unroll
        for (int j = 0; j < 4; ++j)
            #pragma unroll
            for (int r = 0; r < 4; ++r) acc[i][j][r] = 0.f;

#define LOAD_STAGE(s, t) do {                                                  \
    const int _k0 = (t) * 32;                                                  \
    float* _dA = sm + (s) * STAGE_F;                                           \
    float* _dB = _dA + 128 * LDP;                                              \
    _Pragma("unroll")                                                          \
    for (int _i = 0; _i < 4; ++_i) {                                           \
        int _row = lrow + _i * 32;                                             \
        int _ar = row0 + _row; if (_ar > MROWS - 1) _ar = MROWS - 1;           \
        cpa16(smem_u32(_dA + _row * LDP + lseg * 4),                           \
              A + (long)_ar * HIDDEN + _k0 + lseg * 4);                        \
        cpa16(smem_u32(_dB + _row * LDP + lseg * 4),                           \
              Bt + (long)(col0 + _row) * HIDDEN + _k0 + lseg * 4);             \
    }                                                                          \
    asm volatile("cp.async.commit_group;" ::: "memory");                       \
} while (0)

    LOAD_STAGE(0, 0);
    LOAD_STAGE(1, 1);

    for (int t = 0; t < 24; ++t) {
        if (t < 23) asm volatile("cp.async.wait_group 1;" ::: "memory");
        else        asm volatile("cp.async.wait_group 0;" ::: "memory");
        __syncthreads();              // prev-chunk compute done + data visible

        if (t < 22) LOAD_STAGE((t + 2) % 3, t + 2);

        const float* As = sm + (t % 3) * STAGE_F;
        const float* Bs = As + 128 * LDP;

        uint32_t a[2][4][4], b[2][4][2];

#define LOAD_FRAGS(bu, k8_) do {                                               \
    const int _kb = (k8_) * 8;                                                 \
    _Pragma("unroll")                                                          \
    for (int _mi = 0; _mi < 4; ++_mi) {                                        \
        const int _r = wm + _mi * 16 + gid;                                    \
        a[bu][_mi][0] = rna_u(As[_r       * LDP + _kb + tg]);                  \
        a[bu][_mi][1] = rna_u(As[(_r + 8) * LDP + _kb + tg]);                  \
        a[bu][_mi][2] = rna_u(As[_r       * LDP + _kb + tg + 4]);              \
        a[bu][_mi][3] = rna_u(As[(_r + 8) * LDP + _kb + tg + 4]);              \
    }                                                                          \
    _Pragma("unroll")                                                          \
    for (int _nj = 0; _nj < 4; ++_nj) {                                        \
        const int _n = wn + _nj * 8 + gid;                                     \
        b[bu][_nj][0] = __float_as_uint(Bs[_n * LDP + _kb + tg]);              \
        b[bu][_nj][1] = __float_as_uint(Bs[_n * LDP + _kb + tg + 4]);          \
    }                                                                          \
} while (0)

        LOAD_FRAGS(0, 0);
        #pragma unroll
        for (int k8 = 0; k8 < 4; ++k8) {
            const int cur = k8 & 1;
            if (k8 < 3) LOAD_FRAGS(!cur ? 1 : 0, k8 + 1);
            #pragma unroll
            for (int mi = 0; mi < 4; ++mi)
                #pragma unroll
                for (int nj = 0; nj < 4; ++nj)
                    mma_tf32(acc[mi][nj], a[cur][mi], b[cur][nj]);
        }
#undef LOAD_FRAGS
    }
#undef LOAD_STAGE

    // epilogue
    #pragma unroll
    for (int nj = 0; nj < 4; ++nj) {
        const int cb = col0 + wn + nj * 8 + tg * 2;
        const float bx = bias[cb];
        const float by = bias[cb + 1];
        #pragma unroll
        for (int mi = 0; mi < 4; ++mi) {
            const int r = row0 + wm + mi * 16 + gid;
            if (r < MROWS) {
                float2 v = make_float2(acc[mi][nj][0] + bx, acc[mi][nj][1] + by);
                *(float2*)(C + (long)r * HIDDEN + cb) = v;
            }
            if (r + 8 < MROWS) {
                float2 v = make_float2(acc[mi][nj][2] + bx, acc[mi][nj][3] + by);
                *(float2*)(C + (long)(r + 8) * HIDDEN + cb) = v;
            }
        }
    }
}

// ---------------------------------------------------------------------------
// Low-rank projection on tensor cores:
//   OUT[b][k][c] = sum_s Et[k][s] * SRC[b*SEQ+s][c],  K-dim padded to 224
// (Et zero-padded beyond s=196, so clamped SRC rows contribute 0.)
// CTA tile 64x128, 8 warps (2x4, warp tile 32x32), grid (6, BATCH, 2).
// ---------------------------------------------------------------------------
#define PLDB 132
#define PSTAGE_F (64 * LDP + 32 * PLDB)     // 2304 + 4224 = 6528 floats
#define PROJ_SMEM (3 * PSTAGE_F * 4)        // 78336 bytes

__global__ __launch_bounds__(256, 2) void proj_mma(
    const float* __restrict__ Et2,   // [2][KRANK][KPAD]
    const float* __restrict__ K_,    // g_K
    const float* __restrict__ V_,    // g_V
    float* __restrict__ PK_, float* __restrict__ PV_)
{
    extern __shared__ float sm[];
    const int zsel = blockIdx.z;
    const float* __restrict__ Et  = Et2 + (long)zsel * KRANK * KPAD;
    const float* __restrict__ SRC = zsel ? V_ : K_;
    float* __restrict__ OUT       = zsel ? PV_ : PK_;

    const int tid  = threadIdx.x;
    const int wid  = tid >> 5;
    const int lane = tid & 31;
    const int gid  = lane >> 2;
    const int tg   = lane & 3;
    const int wm   = (wid >> 2) * 32;
    const int wn   = (wid & 3) * 32;
    const int col0 = blockIdx.x * 128;
    const int b    = blockIdx.y;

    float acc[2][4][4];
    #pragma unroll
    for (int i = 0; i < 2; ++i)
        #pragma unroll
        for (int j = 0; j < 4; ++j)
            #pragma unroll
            for (int r = 0; r < 4; ++r) acc[i][j][r] = 0.f;

#define PLOAD_STAGE(s, t) do {                                                 \
    const int _k0 = (t) * 32;                                                  \
    float* _dA = sm + (s) * PSTAGE_F;                                          \
    float* _dB = _dA + 64 * LDP;                                               \
    _Pragma("unroll")                                                          \
    for (int _i = 0; _i < 2; ++_i) {                                           \
        int _idx = _i * 256 + tid;                                             \
        int _row = _idx >> 3, _seg = _idx & 7;                                 \
        cpa16(smem_u32(_dA + _row * LDP + _seg * 4),                           \
              Et + (long)_row * KPAD + _k0 + _seg * 4);                        \
    }                                                                          \
    _Pragma("unroll")                                                          \
    for (int _i = 0; _i < 4; ++_i) {                                           \
        int _idx = _i * 256 + tid;                                             \
        int _row = _idx >> 5, _seg = _idx & 31;                                \
        int _s = _k0 + _row; if (_s > SEQ - 1) _s = SEQ - 1;                   \
        cpa16(smem_u32(_dB + _row * PLDB + _seg * 4),                          \
              SRC + ((long)b * SEQ + _s) * HIDDEN + col0 + _seg * 4);          \
    }                                                                          \
    asm volatile("cp.async.commit_group;" ::: "memory");                       \
} while (0)

    PLOAD_STAGE(0, 0);
    PLOAD_STAGE(1, 1);

    for (int t = 0; t < 7; ++t) {
        if (t < 6) asm volatile("cp.async.wait_group 1;" ::: "memory");
        else       asm volatile("cp.async.wait_group 0;" ::: "memory");
        __syncthreads();

        if (t < 5) PLOAD_STAGE((t + 2) % 3, t + 2);

        const float* As = sm + (t % 3) * PSTAGE_F;
        const float* Bs = As + 64 * LDP;

        #pragma unroll
        for (int k8 = 0; k8 < 4; ++k8) {
            const int kb = k8 * 8;
            uint32_t a[2][4], bb[4][2];
            #pragma unroll
            for (int mi = 0; mi < 2; ++mi) {
                const int r = wm + mi * 16 + gid;
                a[mi][0] = __float_as_uint(As[r       * LDP + kb + tg]);
                a[mi][1] = __float_as_uint(As[(r + 8) * LDP + kb + tg]);
                a[mi][2] = __float_as_uint(As[r       * LDP + kb + tg + 4]);
                a[mi][3] = __float_as_uint(As[(r + 8) * LDP + kb + tg + 4]);
            }
            #pragma unroll
            for (int nj = 0; nj < 4; ++nj) {
                const int n = wn + nj * 8 + gid;
                bb[nj][0] = rna_u(Bs[(kb + tg)     * PLDB + n]);
                bb[nj][1] = rna_u(Bs[(kb + tg + 4) * PLDB + n]);
            }
            #pragma unroll
            for (int mi = 0; mi < 2; ++mi)
                #pragma unroll
                for (int nj = 0; nj < 4; ++nj)
                    mma_tf32(acc[mi][nj], a[mi], bb[nj]);
        }
    }
#undef PLOAD_STAGE

    #pragma unroll
    for (int nj = 0; nj < 4; ++nj) {
        const int cb = col0 + wn + nj * 8 + tg * 2;
        #pragma unroll
        for (int mi = 0; mi < 2; ++mi) {
            const int r = wm + mi * 16 + gid;
            float2 v0 = make_float2(acc[mi][nj][0], acc[mi][nj][1]);
            float2 v1 = make_float2(acc[mi][nj][2], acc[mi][nj][3]);
            *(float2*)(OUT + ((long)b * KRANK + r)     * HIDDEN + cb) = v0;
            *(float2*)(OUT + ((long)b * KRANK + r + 8) * HIDDEN + cb) = v1;
        }
    }
}

// ---------------------------------------------------------------------------
// Weight transpose + tf32 round: W[k][n] -> T[n][k], 4 weights via blockIdx.z
// ---------------------------------------------------------------------------
__global__ __launch_bounds__(256) void wtrans_round4(
    const float* __restrict__ W0, const float* __restrict__ W1,
    const float* __restrict__ W2, const float* __restrict__ W3,
    float* __restrict__ Tbase)
{
    const float* W = (blockIdx.z == 0) ? W0 : (blockIdx.z == 1) ? W1
                   : (blockIdx.z == 2) ? W2 : W3;
    float* T = Tbase + (long)blockIdx.z * HH;

    __shared__ float t[32][33];
    const int bx = blockIdx.x * 32;   // n
    const int by = blockIdx.y * 32;   // k
    const int x = threadIdx.x & 31, y = threadIdx.x >> 5;
    #pragma unroll
    for (int i = 0; i < 32; i += 8)
        t[y + i][x] = W[(by + y + i) * HIDDEN + bx + x];
    __syncthreads();
    #pragma unroll
    for (int i = 0; i < 32; i += 8)
        T[(bx + y + i) * HIDDEN + by + x] = rna_tf32(t[x][y + i]);
}

// ---------------------------------------------------------------------------
// E^T prep: Et[z][m][s] = rna(E_z[s][m]) for s<197 else 0
// ---------------------------------------------------------------------------
__global__ __launch_bounds__(256) void et_prep(
    const float* __restrict__ Ek, const float* __restrict__ Ev,
    float* __restrict__ Et2)
{
    int idx = blockIdx.x * 256 + threadIdx.x;
    if (idx >= 2 * KRANK * KPAD) return;
    int z = idx / (KRANK * KPAD);
    int r = idx % (KRANK * KPAD);
    int m = r / KPAD, s = r % KPAD;
    const float* E = z ? Ev : Ek;
    Et2[idx] = (s < SEQ) ? rna_tf32(E[s * KRANK + m]) : 0.f;
}

// ---------------------------------------------------------------------------
// Fused low-rank attention per (b,h) (fp32)
// ---------------------------------------------------------------------------
__global__ __launch_bounds__(128) void lowrank_attn(
    const float* __restrict__ Q, const float* __restrict__ PK,
    const float* __restrict__ PV, float* __restrict__ CTX)
{
    const int h = blockIdx.x;
    const int b = blockIdx.y;

    __shared__ float pk_s[64 * 65];
    __shared__ float pv_s[64 * 64];
    __shared__ float qs[4][64];
    __shared__ float ps[4][64];

    const int tid  = threadIdx.x;
    const int w    = tid >> 5;
    const int lane = tid & 31;

    const float* pkg = PK + ((long)b * KRANK) * HIDDEN + h * HDIM;
    const float* pvg = PV + ((long)b * KRANK) * HIDDEN + h * HDIM;
    for (int i = tid; i < 64 * 64; i += 128) {
        int k = i >> 6, d = i & 63;
        pk_s[k * 65 + d] = pkg[(long)k * HIDDEN + d];
        pv_s[k * 64 + d] = pvg[(long)k * HIDDEN + d];
    }
    __syncthreads();

    const float scale = 0.125f;

    for (int s = w; s < SEQ; s += 4) {
        const float* qg = Q + ((long)b * SEQ + s) * HIDDEN + h * HDIM;
        qs[w][lane]      = qg[lane];
        qs[w][lane + 32] = qg[lane + 32];
        __syncwarp();

        float s0 = 0.f, s1 = 0.f;
        const float* p0 = &pk_s[lane * 65];
        const float* p1 = &pk_s[(lane + 32) * 65];
        #pragma unroll
        for (int d = 0; d < 64; ++d) {
            float qd = qs[w][d];
            s0 = fmaf(qd, p0[d], s0);
            s1 = fmaf(qd, p1[d], s1);
        }
        s0 *= scale; s1 *= scale;

        float mx = fmaxf(s0, s1);
        #pragma unroll
        for (int o = 16; o > 0; o >>= 1)
            mx = fmaxf(mx, __shfl_xor_sync(0xffffffffu, mx, o));
        float e0 = expf(s0 - mx);
        float e1 = expf(s1 - mx);
        float sm = e0 + e1;
        #pragma unroll
        for (int o = 16; o > 0; o >>= 1)
            sm += __shfl_xor_sync(0xffffffffu, sm, o);
        float inv = 1.f / sm;
        ps[w][lane]      = e0 * inv;
        ps[w][lane + 32] = e1 * inv;
        __syncwarp();

        float c0 = 0.f, c1 = 0.f;
        #pragma unroll
        for (int k = 0; k < 64; ++k) {
            float p = ps[w][k];
            c0 = fmaf(p, pv_s[k * 64 + lane],      c0);
            c1 = fmaf(p, pv_s[k * 64 + lane + 32], c1);
        }
        float* cg = CTX + ((long)b * SEQ + s) * HIDDEN + h * HDIM;
        cg[lane]      = c0;
        cg[lane + 32] = c1;
        __syncwarp();
    }
}

// ---------------------------------------------------------------------------
// Launch orchestration
// ---------------------------------------------------------------------------
extern "C" void kernel_launch(void* const* d_in, const int* in_sizes, int n_in,
                              void* d_out, int out_size)
{
    const float* hs = (const float*)d_in[0];
    const float* Wq = (const float*)d_in[1];
    const float* bq = (const float*)d_in[2];
    const float* Wk = (const float*)d_in[3];
    const float* bk = (const float*)d_in[4];
    const float* Wv = (const float*)d_in[5];
    const float* bv = (const float*)d_in[6];
    const float* Wo = (const float*)d_in[7];
    const float* bo = (const float*)d_in[8];
    const float* Ek = (const float*)d_in[9];
    const float* Ev = (const float*)d_in[10];
    float* out = (float*)d_out;

    float *pQ, *pK, *pV, *pCTX, *pPK, *pPV, *pWt, *pEt;
    cudaGetSymbolAddress((void**)&pQ,   g_Q);
    cudaGetSymbolAddress((void**)&pK,   g_K);
    cudaGetSymbolAddress((void**)&pV,   g_V);
    cudaGetSymbolAddress((void**)&pCTX, g_CTX);
    cudaGetSymbolAddress((void**)&pPK,  g_PK);
    cudaGetSymbolAddress((void**)&pPV,  g_PV);
    cudaGetSymbolAddress((void**)&pWt,  g_Wt);
    cudaGetSymbolAddress((void**)&pEt,  g_Et);

    cudaFuncSetAttribute(gemm_tf32, cudaFuncAttributeMaxDynamicSharedMemorySize,
                         GEMM_SMEM);
    cudaFuncSetAttribute(proj_mma, cudaFuncAttributeMaxDynamicSharedMemorySize,
                         PROJ_SMEM);

    // prep: weight transpose+round (all four), E^T prep
    dim3 tgrid(HIDDEN / 32, HIDDEN / 32, 4);          // (24,24,4)
    wtrans_round4<<<tgrid, 256>>>(Wq, Wk, Wv, Wo, pWt);
    const int etN = 2 * KRANK * KPAD;
    et_prep<<<(etN + 255) / 256, 256>>>(Ek, Ev, pEt);

    // fused QKV projections (grid.z selects weight/bias/output)
    GSet sq = { pWt + 0 * HH, bq, pQ };
    GSet sk = { pWt + 1 * HH, bk, pK };
    GSet sv = { pWt + 2 * HH, bv, pV };
    dim3 ggrid3(HIDDEN / 128, (MROWS + 127) / 128, 3);   // (6, 99, 3)
    gemm_tf32<<<ggrid3, 256, GEMM_SMEM>>>(hs, sq, sk, sv);

    // low-rank projections on tensor cores (z: 0=K, 1=V)
    dim3 pgrid(HIDDEN / 128, BATCH, 2);                  // (6, 64, 2)
    proj_mma<<<pgrid, 256, PROJ_SMEM>>>(pEt, pK, pV, pPK, pPV);

    // attention (fp32)
    dim3 attnGrid(HEADS, BATCH);
    lowrank_attn<<<attnGrid, 128>>>(pQ, pPK, pPV, pCTX);

    // output projection
    GSet so = { pWt + 3 * HH, bo, out };
    dim3 ggrid1(HIDDEN / 128, (MROWS + 127) / 128, 1);
    gemm_tf32<<<ggrid1, 256, GEMM_SMEM>>>(pCTX, so, so, so);
}

// round 10
// speedup vs baseline: 2.6826x; 1.0135x over previous
#include <cuda_runtime.h>
#include <cuda_bf16.h>
#include <cstdint>
#include <math.h>

// Problem constants
#define BATCH   64
#define SEQ     197
#define HIDDEN  768
#define HEADS   12
#define HDIM    64
#define KRANK   64
#define MROWS   (BATCH * SEQ)          // 12608
#define HH      (HIDDEN * HIDDEN)
#define KPAD    224                    // SEQ padded to 7*32

// ---------------------------------------------------------------------------
// Scratch (no allocations allowed): device globals
// ---------------------------------------------------------------------------
__device__ float g_Q  [MROWS * HIDDEN];
__device__ float g_K  [MROWS * HIDDEN];
__device__ float g_V  [MROWS * HIDDEN];
__device__ float g_CTX[MROWS * HIDDEN];
__device__ float g_PK [BATCH * KRANK * HIDDEN];
__device__ float g_PV [BATCH * KRANK * HIDDEN];
__device__ float g_Wt [4 * HH];            // transposed + rounded + col-permuted weights
__device__ float g_Et [2 * KRANK * KPAD];  // E^T, tf32-rounded, zero-padded

// ---------------------------------------------------------------------------
// Helpers
// ---------------------------------------------------------------------------
static __device__ __forceinline__ uint32_t smem_u32(const void* p) {
    uint32_t a;
    asm("{ .reg .u64 t; cvta.to.shared.u64 t, %1; cvt.u32.u64 %0, t; }"
        : "=r"(a) : "l"(p));
    return a;
}
static __device__ __forceinline__ void cpa16(uint32_t s, const void* g) {
    asm volatile("cp.async.cg.shared.global [%0], [%1], 16;" :: "r"(s), "l"(g));
}
static __device__ __forceinline__ float rna_tf32(float x) {
    uint32_t u;
    asm("cvt.rna.tf32.f32 %0, %1;" : "=r"(u) : "f"(x));
    return __uint_as_float(u);
}
static __device__ __forceinline__ uint32_t rna_u(float x) {
    uint32_t u;
    asm("cvt.rna.tf32.f32 %0, %1;" : "=r"(u) : "f"(x));
    return u;
}
static __device__ __forceinline__ void mma_tf32(
    float* c, const uint32_t* a, uint32_t b0, uint32_t b1)
{
    asm volatile(
        "mma.sync.aligned.m16n8k8.row.col.f32.tf32.tf32.f32 "
        "{%0,%1,%2,%3}, {%4,%5,%6,%7}, {%8,%9}, {%0,%1,%2,%3};"
        : "+f"(c[0]), "+f"(c[1]), "+f"(c[2]), "+f"(c[3])
        : "r"(a[0]), "r"(a[1]), "r"(a[2]), "r"(a[3]), "r"(b0), "r"(b1));
}

struct GSet { const float* Bt; const float* bias; float* C; };

// ---------------------------------------------------------------------------
// tf32 HMMA GEMM: C[M,768] = A[M,768] @ W + bias
//   W transposed [n][k], tf32-rounded, k-cols permuted per 32-block:
//   p(c) = (c&3)*8 + (c>>2)  -> per-thread B fragments become float4 loads.
//   A raw fp32, rounded per-fragment in registers.
// CTA 128x128, 8 warps (2x4, warp tile 64x32), K-chunk 32, 3-stage cp.async,
// one __syncthreads per chunk, 2 CTAs/SM for stall overlap.
// ---------------------------------------------------------------------------
#define LDP 36
#define STAGE_F (2 * 128 * LDP)          // 9216 floats
#define GEMM_SMEM (3 * STAGE_F * 4)      // 110592 bytes

__global__ __launch_bounds__(256, 2) void gemm_tf32(
    const float* __restrict__ A, GSet s0, GSet s1, GSet s2)
{
    extern __shared__ float sm[];
    const GSet g = (blockIdx.z == 0) ? s0 : (blockIdx.z == 1) ? s1 : s2;
    const float* __restrict__ Bt   = g.Bt;
    const float* __restrict__ bias = g.bias;
    float* __restrict__ C          = g.C;

    const int tid  = threadIdx.x;
    const int wid  = tid >> 5;
    const int lane = tid & 31;
    const int gid  = lane >> 2;
    const int tg   = lane & 3;
    const int wm   = (wid >> 2) * 64;
    const int wn   = (wid & 3) * 32;
    const int row0 = blockIdx.y * 128;
    const int col0 = blockIdx.x * 128;

    const int lrow = tid >> 3;
    const int lseg = tid & 7;

    float acc[4][4][4];
    #pragma unroll
    for (int i = 0; i < 4; ++i)
        #pragma unroll
        for (int j = 0; j < 4; ++j)
            #pragma unroll
            for (int r = 0; r < 4; ++r) acc[i][j][r] = 0.f;

#define LOAD_STAGE(s, t) do {                                                  \
    const int _k0 = (t) * 32;                                                  \
    float* _dA = sm + (s) * STAGE_F;                                           \
    float* _dB = _dA + 128 * LDP;                                              \
    _Pragma("unroll")                                                          \
    for (int _i = 0; _i < 4; ++_i) {                                           \
        int _row = lrow + _i * 32;                                             \
        int _ar = row0 + _row; if (_ar > MROWS - 1) _ar = MROWS - 1;           \
        cpa16(smem_u32(_dA + _row * LDP + lseg * 4),                           \
              A + (long)_ar * HIDDEN + _k0 + lseg * 4);                        \
        cpa16(smem_u32(_dB + _row * LDP + lseg * 4),                           \
              Bt + (long)(col0 + _row) * HIDDEN + _k0 + lseg * 4);             \
    }                                                                          \
    asm volatile("cp.async.commit_group;" ::: "memory");                       \
} while (0)

    LOAD_STAGE(0, 0);
    LOAD_STAGE(1, 1);

    for (int t = 0; t < 24; ++t) {
        if (t < 23) asm volatile("cp.async.wait_group 1;" ::: "memory");
        else        asm volatile("cp.async.wait_group 0;" ::: "memory");
        __syncthreads();              // prev-chunk compute done + data visible

        if (t < 22) LOAD_STAGE((t + 2) % 3, t + 2);

        const float* As = sm + (t % 3) * STAGE_F;
        const float* Bs = As + 128 * LDP;

        uint32_t a[4][4];
        float4 bv[4];

        #pragma unroll
        for (int k8 = 0; k8 < 4; ++k8) {
            const int kb = k8 * 8;
            if ((k8 & 1) == 0) {
                // permuted layout: one float4 covers this k8-pair's B frags
                #pragma unroll
                for (int nj = 0; nj < 4; ++nj) {
                    const int n = wn + nj * 8 + gid;
                    bv[nj] = *(const float4*)&Bs[n * LDP + tg * 8 + (k8 >> 1) * 4];
                }
            }
            #pragma unroll
            for (int mi = 0; mi < 4; ++mi) {
                const int r = wm + mi * 16 + gid;
                a[mi][0] = rna_u(As[r       * LDP + kb + tg]);
                a[mi][1] = rna_u(As[(r + 8) * LDP + kb + tg]);
                a[mi][2] = rna_u(As[r       * LDP + kb + tg + 4]);
                a[mi][3] = rna_u(As[(r + 8) * LDP + kb + tg + 4]);
            }
            #pragma unroll
            for (int mi = 0; mi < 4; ++mi)
                #pragma unroll
                for (int nj = 0; nj < 4; ++nj) {
                    const uint32_t b0 = (k8 & 1) ? __float_as_uint(bv[nj].z)
                                                 : __float_as_uint(bv[nj].x);
                    const uint32_t b1 = (k8 & 1) ? __float_as_uint(bv[nj].w)
                                                 : __float_as_uint(bv[nj].y);
                    mma_tf32(acc[mi][nj], a[mi], b0, b1);
                }
        }
    }
#undef LOAD_STAGE

    // epilogue
    #pragma unroll
    for (int nj = 0; nj < 4; ++nj) {
        const int cb = col0 + wn + nj * 8 + tg * 2;
        const float bx = bias[cb];
        const float by = bias[cb + 1];
        #pragma unroll
        for (int mi = 0; mi < 4; ++mi) {
            const int r = row0 + wm + mi * 16 + gid;
            if (r < MROWS) {
                float2 v = make_float2(acc[mi][nj][0] + bx, acc[mi][nj][1] + by);
                *(float2*)(C + (long)r * HIDDEN + cb) = v;
            }
            if (r + 8 < MROWS) {
                float2 v = make_float2(acc[mi][nj][2] + bx, acc[mi][nj][3] + by);
                *(float2*)(C + (long)(r + 8) * HIDDEN + cb) = v;
            }
        }
    }
}

// ---------------------------------------------------------------------------
// Low-rank projection on tensor cores:
//   OUT[b][k][c] = sum_s Et[k][s] * SRC[b*SEQ+s][c],  K-dim padded to 224
// CTA tile 64x128, 8 warps (2x4, warp tile 32x32), grid (6, BATCH, 2).
// ---------------------------------------------------------------------------
#define PLDB 132
#define PSTAGE_F (64 * LDP + 32 * PLDB)     // 6528 floats
#define PROJ_SMEM (3 * PSTAGE_F * 4)        // 78336 bytes

__global__ __launch_bounds__(256, 2) void proj_mma(
    const float* __restrict__ Et2,   // [2][KRANK][KPAD]
    const float* __restrict__ K_,
    const float* __restrict__ V_,
    float* __restrict__ PK_, float* __restrict__ PV_)
{
    extern __shared__ float sm[];
    const int zsel = blockIdx.z;
    const float* __restrict__ Et  = Et2 + (long)zsel * KRANK * KPAD;
    const float* __restrict__ SRC = zsel ? V_ : K_;
    float* __restrict__ OUT       = zsel ? PV_ : PK_;

    const int tid  = threadIdx.x;
    const int wid  = tid >> 5;
    const int lane = tid & 31;
    const int gid  = lane >> 2;
    const int tg   = lane & 3;
    const int wm   = (wid >> 2) * 32;
    const int wn   = (wid & 3) * 32;
    const int col0 = blockIdx.x * 128;
    const int b    = blockIdx.y;

    float acc[2][4][4];
    #pragma unroll
    for (int i = 0; i < 2; ++i)
        #pragma unroll
        for (int j = 0; j < 4; ++j)
            #pragma unroll
            for (int r = 0; r < 4; ++r) acc[i][j][r] = 0.f;

#define PLOAD_STAGE(s, t) do {                                                 \
    const int _k0 = (t) * 32;                                                  \
    float* _dA = sm + (s) * PSTAGE_F;                                          \
    float* _dB = _dA + 64 * LDP;                                               \
    _Pragma("unroll")                                                          \
    for (int _i = 0; _i < 2; ++_i) {                                           \
        int _idx = _i * 256 + tid;                                             \
        int _row = _idx >> 3, _seg = _idx & 7;                                 \
        cpa16(smem_u32(_dA + _row * LDP + _seg * 4),                           \
              Et + (long)_row * KPAD + _k0 + _seg * 4);                        \
    }                                                                          \
    _Pragma("unroll")                                                          \
    for (int _i = 0; _i < 4; ++_i) {                                           \
        int _idx = _i * 256 + tid;                                             \
        int _row = _idx >> 5, _seg = _idx & 31;                                \
        int _s = _k0 + _row; if (_s > SEQ - 1) _s = SEQ - 1;                   \
        cpa16(smem_u32(_dB + _row * PLDB + _seg * 4),                          \
              SRC + ((long)b * SEQ + _s) * HIDDEN + col0 + _seg * 4);          \
    }                                                                          \
    asm volatile("cp.async.commit_group;" ::: "memory");                       \
} while (0)

    PLOAD_STAGE(0, 0);
    PLOAD_STAGE(1, 1);

    for (int t = 0; t < 7; ++t) {
        if (t < 6) asm volatile("cp.async.wait_group 1;" ::: "memory");
        else       asm volatile("cp.async.wait_group 0;" ::: "memory");
        __syncthreads();

        if (t < 5) PLOAD_STAGE((t + 2) % 3, t + 2);

        const float* As = sm + (t % 3) * PSTAGE_F;
        const float* Bs = As + 64 * LDP;

        #pragma unroll
        for (int k8 = 0; k8 < 4; ++k8) {
            const int kb = k8 * 8;
            uint32_t a[2][4], bb[4][2];
            #pragma unroll
            for (int mi = 0; mi < 2; ++mi) {
                const int r = wm + mi * 16 + gid;
                a[mi][0] = __float_as_uint(As[r       * LDP + kb + tg]);
                a[mi][1] = __float_as_uint(As[(r + 8) * LDP + kb + tg]);
                a[mi][2] = __float_as_uint(As[r       * LDP + kb + tg + 4]);
                a[mi][3] = __float_as_uint(As[(r + 8) * LDP + kb + tg + 4]);
            }
            #pragma unroll
            for (int nj = 0; nj < 4; ++nj) {
                const int n = wn + nj * 8 + gid;
                bb[nj][0] = rna_u(Bs[(kb + tg)     * PLDB + n]);
                bb[nj][1] = rna_u(Bs[(kb + tg + 4) * PLDB + n]);
            }
            #pragma unroll
            for (int mi = 0; mi < 2; ++mi)
                #pragma unroll
                for (int nj = 0; nj < 4; ++nj)
                    mma_tf32(acc[mi][nj], a[mi], bb[nj][0], bb[nj][1]);
        }
    }
#undef PLOAD_STAGE

    #pragma unroll
    for (int nj = 0; nj < 4; ++nj) {
        const int cb = col0 + wn + nj * 8 + tg * 2;
        #pragma unroll
        for (int mi = 0; mi < 2; ++mi) {
            const int r = wm + mi * 16 + gid;
            float2 v0 = make_float2(acc[mi][nj][0], acc[mi][nj][1]);
            float2 v1 = make_float2(acc[mi][nj][2], acc[mi][nj][3]);
            *(float2*)(OUT + ((long)b * KRANK + r)     * HIDDEN + cb) = v0;
            *(float2*)(OUT + ((long)b * KRANK + r + 8) * HIDDEN + cb) = v1;
        }
    }
}

// ---------------------------------------------------------------------------
// Weight transpose + tf32 round + per-32-block column permutation:
//   T[n][kblk + p(klocal)] = rna(W[k][n]),  p(c) = (c&3)*8 + (c>>2)
// ---------------------------------------------------------------------------
__global__ __launch_bounds__(256) void wtrans_round4(
    const float* __restrict__ W0, const float* __restrict__ W1,
    const float* __restrict__ W2, const float* __restrict__ W3,
    float* __restrict__ Tbase)
{
    const float* W = (blockIdx.z == 0) ? W0 : (blockIdx.z == 1) ? W1
                   : (blockIdx.z == 2) ? W2 : W3;
    float* T = Tbase + (long)blockIdx.z * HH;

    __shared__ float t[32][33];
    const int bx = blockIdx.x * 32;   // n
    const int by = blockIdx.y * 32;   // k block (32-aligned)
    const int x = threadIdx.x & 31, y = threadIdx.x >> 5;
    #pragma unroll
    for (int i = 0; i < 32; i += 8)
        t[y + i][x] = W[(by + y + i) * HIDDEN + bx + x];
    __syncthreads();
    const int p = (x & 3) * 8 + (x >> 2);   // permuted k position within block
    #pragma unroll
    for (int i = 0; i < 32; i += 8)
        T[(bx + y + i) * HIDDEN + by + p] = rna_tf32(t[x][y + i]);
}

// ---------------------------------------------------------------------------
// E^T prep: Et[z][m][s] = rna(E_z[s][m]) for s<197 else 0
// ---------------------------------------------------------------------------
__global__ __launch_bounds__(256) void et_prep(
    const float* __restrict__ Ek, const float* __restrict__ Ev,
    float* __restrict__ Et2)
{
    int idx = blockIdx.x * 256 + threadIdx.x;
    if (idx >= 2 * KRANK * KPAD) return;
    int z = idx / (KRANK * KPAD);
    int r = idx % (KRANK * KPAD);
    int m = r / KPAD, s = r % KPAD;
    const float* E = z ? Ev : Ek;
    Et2[idx] = (s < SEQ) ? rna_tf32(E[s * KRANK + m]) : 0.f;
}

// ---------------------------------------------------------------------------
// Fused low-rank attention per (b,h) (fp32)
// ---------------------------------------------------------------------------
__global__ __launch_bounds__(128) void lowrank_attn(
    const float* __restrict__ Q, const float* __restrict__ PK,
    const float* __restrict__ PV, float* __restrict__ CTX)
{
    const int h = blockIdx.x;
    const int b = blockIdx.y;

    __shared__ float pk_s[64 * 65];
    __shared__ float pv_s[64 * 64];
    __shared__ float qs[4][64];
    __shared__ float ps[4][64];

    const int tid  = threadIdx.x;
    const int w    = tid >> 5;
    const int lane = tid & 31;

    const float* pkg = PK + ((long)b * KRANK) * HIDDEN + h * HDIM;
    const float* pvg = PV + ((long)b * KRANK) * HIDDEN + h * HDIM;
    for (int i = tid; i < 64 * 64; i += 128) {
        int k = i >> 6, d = i & 63;
        pk_s[k * 65 + d] = pkg[(long)k * HIDDEN + d];
        pv_s[k * 64 + d] = pvg[(long)k * HIDDEN + d];
    }
    __syncthreads();

    const float scale = 0.125f;

    for (int s = w; s < SEQ; s += 4) {
        const float* qg = Q + ((long)b * SEQ + s) * HIDDEN + h * HDIM;
        qs[w][lane]      = qg[lane];
        qs[w][lane + 32] = qg[lane + 32];
        __syncwarp();

        float s0 = 0.f, s1 = 0.f;
        const float* p0 = &pk_s[lane * 65];
        const float* p1 = &pk_s[(lane + 32) * 65];
        #pragma unroll
        for (int d = 0; d < 64; ++d) {
            float qd = qs[w][d];
            s0 = fmaf(qd, p0[d], s0);
            s1 = fmaf(qd, p1[d], s1);
        }
        s0 *= scale; s1 *= scale;

        float mx = fmaxf(s0, s1);
        #pragma unroll
        for (int o = 16; o > 0; o >>= 1)
            mx = fmaxf(mx, __shfl_xor_sync(0xffffffffu, mx, o));
        float e0 = expf(s0 - mx);
        float e1 = expf(s1 - mx);
        float sm = e0 + e1;
        #pragma unroll
        for (int o = 16; o > 0; o >>= 1)
            sm += __shfl_xor_sync(0xffffffffu, sm, o);
        float inv = 1.f / sm;
        ps[w][lane]      = e0 * inv;
        ps[w][lane + 32] = e1 * inv;
        __syncwarp();

        float c0 = 0.f, c1 = 0.f;
        #pragma unroll
        for (int k = 0; k < 64; ++k) {
            float p = ps[w][k];
            c0 = fmaf(p, pv_s[k * 64 + lane],      c0);
            c1 = fmaf(p, pv_s[k * 64 + lane + 32], c1);
        }
        float* cg = CTX + ((long)b * SEQ + s) * HIDDEN + h * HDIM;
        cg[lane]      = c0;
        cg[lane + 32] = c1;
        __syncwarp();
    }
}

// ---------------------------------------------------------------------------
// Launch orchestration
// ---------------------------------------------------------------------------
extern "C" void kernel_launch(void* const* d_in, const int* in_sizes, int n_in,
                              void* d_out, int out_size)
{
    const float* hs = (const float*)d_in[0];
    const float* Wq = (const float*)d_in[1];
    const float* bq = (const float*)d_in[2];
    const float* Wk = (const float*)d_in[3];
    const float* bk = (const float*)d_in[4];
    const float* Wv = (const float*)d_in[5];
    const float* bv = (const float*)d_in[6];
    const float* Wo = (const float*)d_in[7];
    const float* bo = (const float*)d_in[8];
    const float* Ek = (const float*)d_in[9];
    const float* Ev = (const float*)d_in[10];
    float* out = (float*)d_out;

    float *pQ, *pK, *pV, *pCTX, *pPK, *pPV, *pWt, *pEt;
    cudaGetSymbolAddress((void**)&pQ,   g_Q);
    cudaGetSymbolAddress((void**)&pK,   g_K);
    cudaGetSymbolAddress((void**)&pV,   g_V);
    cudaGetSymbolAddress((void**)&pCTX, g_CTX);
    cudaGetSymbolAddress((void**)&pPK,  g_PK);
    cudaGetSymbolAddress((void**)&pPV,  g_PV);
    cudaGetSymbolAddress((void**)&pWt,  g_Wt);
    cudaGetSymbolAddress((void**)&pEt,  g_Et);

    cudaFuncSetAttribute(gemm_tf32, cudaFuncAttributeMaxDynamicSharedMemorySize,
                         GEMM_SMEM);
    cudaFuncSetAttribute(proj_mma, cudaFuncAttributeMaxDynamicSharedMemorySize,
                         PROJ_SMEM);

    // prep
    dim3 tgrid(HIDDEN / 32, HIDDEN / 32, 4);          // (24,24,4)
    wtrans_round4<<<tgrid, 256>>>(Wq, Wk, Wv, Wo, pWt);
    const int etN = 2 * KRANK * KPAD;
    et_prep<<<(etN + 255) / 256, 256>>>(Ek, Ev, pEt);

    // fused QKV projections
    GSet sq = { pWt + 0 * HH, bq, pQ };
    GSet sk = { pWt + 1 * HH, bk, pK };
    GSet sv = { pWt + 2 * HH, bv, pV };
    dim3 ggrid3(HIDDEN / 128, (MROWS + 127) / 128, 3);   // (6, 99, 3)
    gemm_tf32<<<ggrid3, 256, GEMM_SMEM>>>(hs, sq, sk, sv);

    // low-rank projections
    dim3 pgrid(HIDDEN / 128, BATCH, 2);                  // (6, 64, 2)
    proj_mma<<<pgrid, 256, PROJ_SMEM>>>(pEt, pK, pV, pPK, pPV);

    // attention
    dim3 attnGrid(HEADS, BATCH);
    lowrank_attn<<<attnGrid, 128>>>(pQ, pPK, pPV, pCTX);

    // output projection
    GSet so = { pWt + 3 * HH, bo, out };
    dim3 ggrid1(HIDDEN / 128, (MROWS + 127) / 128, 1);
    gemm_tf32<<<ggrid1, 256, GEMM_SMEM>>>(pCTX, so, so, so);
}